// round 2
// baseline (speedup 1.0000x reference)
#include <cuda_runtime.h>
#include <cuda_bf16.h>
#include <stdint.h>

#define NN 2048
#define DD 1024
#define PP 6
#define BM 128
#define BN 128
#define BK 32
#define NT 16                    // NN / BM
#define NBLK (NT * (NT + 1) / 2) // 136 triangular tiles
#define KST (DD / BK)            // 32 k-stages per part
#define STAGES (PP * KST)        // 192 total stages

// -------- scratch (static device globals: allocation-free) --------
__device__ __nv_bfloat16 g_X[(size_t)PP * NN * DD]; // packed [p][n][d] bf16, 25 MB
__device__ float g_sqn[PP * NN];                    // [p][n] squared norms (of bf16 values)
__device__ int g_mask[NN];                          // 6-bit part visibility mask
__device__ int g_ap[NN];                            // float bits, atomicMax (all vals >= 0)
__device__ int g_an[NN];                            // float bits, atomicMin

// -------- PTX helpers --------
__device__ __forceinline__ void cp_async16(uint32_t dst, const void* src) {
    asm volatile("cp.async.cg.shared.global [%0], [%1], 16;\n" :: "r"(dst), "l"(src));
}
__device__ __forceinline__ void cp_commit() { asm volatile("cp.async.commit_group;\n"); }
template<int W> __device__ __forceinline__ void cp_wait() {
    asm volatile("cp.async.wait_group %0;\n" :: "n"(W));
}
__device__ __forceinline__ void ldsm_x4(uint32_t r[4], uint32_t addr) {
    asm volatile("ldmatrix.sync.aligned.m8n8.x4.shared.b16 {%0,%1,%2,%3}, [%4];\n"
                 : "=r"(r[0]), "=r"(r[1]), "=r"(r[2]), "=r"(r[3]) : "r"(addr));
}
__device__ __forceinline__ void mma_bf16(float c[4], const uint32_t a[4], uint32_t b0, uint32_t b1) {
    asm volatile("mma.sync.aligned.m16n8k16.row.col.f32.bf16.bf16.f32 "
                 "{%0,%1,%2,%3}, {%4,%5,%6,%7}, {%8,%9}, {%0,%1,%2,%3};\n"
                 : "+f"(c[0]), "+f"(c[1]), "+f"(c[2]), "+f"(c[3])
                 : "r"(a[0]), "r"(a[1]), "r"(a[2]), "r"(a[3]), "r"(b0), "r"(b1));
}
__device__ __forceinline__ float fsqrt_approx(float x) {
    float y; asm("sqrt.approx.f32 %0, %1;" : "=f"(y) : "f"(x)); return y;
}

// Conflict-free swizzled byte offset inside a [128 rows x 32 bf16] tile.
// Rows are 64B; pack 2 rows per 128B line; slot = (kc + 4*(r&1)) ^ ((r>>1)&7).
// For any 8 consecutive rows at fixed kc the 8 slots are distinct -> ldmatrix
// phases and cp.async stores are bank-conflict-free.
__device__ __forceinline__ uint32_t tile_off(int r, int kc) {
    return (uint32_t)(((r >> 1) * 128) + ((((kc) + ((r & 1) << 2)) ^ ((r >> 1) & 7)) << 4));
}

// -------- pack: fp32 [n][d][P] -> bf16 [p][n][d]; sqn of bf16 values; masks --------
__global__ void pack_kernel(const float* __restrict__ in, const int* __restrict__ pl) {
    int i = blockIdx.x;
    int tid = threadIdx.x;
    float acc[PP];
#pragma unroll
    for (int p = 0; p < PP; p++) acc[p] = 0.f;
    const float* row = in + (size_t)i * DD * PP;
    for (int dd = tid; dd < DD; dd += 256) {
#pragma unroll
        for (int p = 0; p < PP; p++) {
            float v = row[dd * PP + p];
            __nv_bfloat16 b = __float2bfloat16(v);
            float vb = __bfloat162float(b);
            g_X[((size_t)p * NN + i) * DD + dd] = b;
            acc[p] = fmaf(vb, vb, acc[p]);
        }
    }
    __shared__ float s[8][PP];
    int warp = tid >> 5, lane = tid & 31;
#pragma unroll
    for (int p = 0; p < PP; p++) {
        float v = acc[p];
#pragma unroll
        for (int o = 16; o > 0; o >>= 1) v += __shfl_xor_sync(~0u, v, o);
        if (lane == 0) s[warp][p] = v;
    }
    __syncthreads();
    if (tid < PP) {
        float v = 0.f;
#pragma unroll
        for (int w = 0; w < 8; w++) v += s[w][tid];
        g_sqn[tid * NN + i] = v;
    }
    if (tid == 0) {
        int st = pl[2 * i], en = pl[2 * i + 1];
        g_mask[i] = (int)(((1u << (en + 1)) - 1u) & ~((1u << st) - 1u));
    }
}

__global__ void init_kernel() {
    int i = blockIdx.x * blockDim.x + threadIdx.x;
    if (i < NN) { g_ap[i] = 0; g_an[i] = 0x7f800000; }
}

// -------- main fused tile kernel: 128x128 output tile, triangular grid --------
__global__ void __launch_bounds__(256, 1)
tile_kernel(const int* __restrict__ targets) {
    __shared__ __align__(16) __nv_bfloat16 sAbuf[2][BM * BK];
    __shared__ __align__(16) __nv_bfloat16 sBbuf[2][BN * BK];
    __shared__ float s_sqA[PP * BM], s_sqB[PP * BN];
    __shared__ int s_mA[BM], s_mB[BN], s_tA[BM], s_tB[BN];
    __shared__ int s_rAp[BM], s_rAn[BM], s_cAp[BN], s_cAn[BN];

    // triangular block -> (bi, bj), bi <= bj
    int b = blockIdx.x, bi = 0;
    while (b >= NT - bi) { b -= NT - bi; ++bi; }
    int bj = bi + b;
    int i0 = bi * BM, j0 = bj * BN;

    int tid = threadIdx.x;
    int lane = tid & 31, warp = tid >> 5;
    int wm = warp >> 1, wn = warp & 1; // 4x2 warp grid, warp tile 32x64

    for (int idx = tid; idx < PP * BM; idx += 256) {
        int p = idx >> 7, r = idx & (BM - 1);
        s_sqA[idx] = g_sqn[p * NN + i0 + r];
        s_sqB[idx] = g_sqn[p * NN + j0 + r];
    }
    for (int idx = tid; idx < BM; idx += 256) {
        s_mA[idx] = g_mask[i0 + idx]; s_mB[idx] = g_mask[j0 + idx];
        s_tA[idx] = targets[i0 + idx]; s_tB[idx] = targets[j0 + idx];
        s_rAp[idx] = 0; s_rAn[idx] = 0x7f800000;
        s_cAp[idx] = 0; s_cAn[idx] = 0x7f800000;
    }

    float acc[2][8][4], dst[2][8][4];
#pragma unroll
    for (int mt = 0; mt < 2; mt++)
#pragma unroll
        for (int nt = 0; nt < 8; nt++)
#pragma unroll
            for (int e = 0; e < 4; e++) { acc[mt][nt][e] = 0.f; dst[mt][nt][e] = 0.f; }

    uint32_t sA32[2], sB32[2];
    sA32[0] = (uint32_t)__cvta_generic_to_shared(&sAbuf[0][0]);
    sA32[1] = (uint32_t)__cvta_generic_to_shared(&sAbuf[1][0]);
    sB32[0] = (uint32_t)__cvta_generic_to_shared(&sBbuf[0][0]);
    sB32[1] = (uint32_t)__cvta_generic_to_shared(&sBbuf[1][0]);

    auto issue_load = [&](int s, int buf) {
        int p = s >> 5;            // s / KST
        int k0 = (s & 31) << 5;    // (s % KST) * BK
        const __nv_bfloat16* gA = g_X + ((size_t)p * NN + i0) * DD + k0;
        const __nv_bfloat16* gB = g_X + ((size_t)p * NN + j0) * DD + k0;
#pragma unroll
        for (int q = 0; q < 2; q++) {
            int lin = q * 256 + tid;
            int r = lin >> 2, kc = lin & 3;
            uint32_t off = tile_off(r, kc);
            cp_async16(sA32[buf] + off, gA + (size_t)r * DD + (kc << 3));
            cp_async16(sB32[buf] + off, gB + (size_t)r * DD + (kc << 3));
        }
        cp_commit();
    };

    int rrow = ((lane >> 3) & 1) * 8 + (lane & 7); // ldmatrix row within 16-row tile
    int chalf = lane >> 4;                         // ldmatrix k-chunk half

    auto compute_stage = [&](int buf) {
#pragma unroll
        for (int ks = 0; ks < 2; ks++) {
            int kc = ks * 2 + chalf;
            uint32_t a[2][4];
#pragma unroll
            for (int mt = 0; mt < 2; mt++)
                ldsm_x4(a[mt], sA32[buf] + tile_off(wm * 32 + mt * 16 + rrow, kc));
            uint32_t bfr[4][4];
#pragma unroll
            for (int pr = 0; pr < 4; pr++)
                ldsm_x4(bfr[pr], sB32[buf] + tile_off(wn * 64 + pr * 16 + rrow, kc));
#pragma unroll
            for (int mt = 0; mt < 2; mt++)
#pragma unroll
                for (int nt = 0; nt < 8; nt++)
                    mma_bf16(acc[mt][nt], a[mt], bfr[nt >> 1][nt & 1], bfr[nt >> 1][(nt & 1) + 2]);
        }
    };

    issue_load(0, 0);
    for (int s = 0; s < STAGES; s++) {
        int buf = s & 1;
        if (s + 1 < STAGES) { issue_load(s + 1, buf ^ 1); cp_wait<1>(); }
        else cp_wait<0>();
        __syncthreads();
        compute_stage(buf);
        if ((s & 31) == 31) {
            // end of part p: fold gram -> partial distance, reset acc
            int p = s >> 5;
#pragma unroll
            for (int mt = 0; mt < 2; mt++) {
                int r0 = wm * 32 + mt * 16 + (lane >> 2);
                float sa0 = s_sqA[p * BM + r0];
                float sa1 = s_sqA[p * BM + r0 + 8];
                int ma0 = (s_mA[r0] >> p) & 1;
                int ma1 = (s_mA[r0 + 8] >> p) & 1;
#pragma unroll
                for (int nt = 0; nt < 8; nt++) {
                    int c0 = wn * 64 + nt * 8 + (lane & 3) * 2;
                    float sb0 = s_sqB[p * BN + c0], sb1 = s_sqB[p * BN + c0 + 1];
                    int mb0 = (s_mB[c0] >> p) & 1, mb1 = (s_mB[c0 + 1] >> p) & 1;
                    float pd;
                    pd = fsqrt_approx(fmaxf(sa0 + sb0 - 2.f * acc[mt][nt][0], 1e-12f));
                    if (ma0 & mb0) dst[mt][nt][0] += pd;
                    pd = fsqrt_approx(fmaxf(sa0 + sb1 - 2.f * acc[mt][nt][1], 1e-12f));
                    if (ma0 & mb1) dst[mt][nt][1] += pd;
                    pd = fsqrt_approx(fmaxf(sa1 + sb0 - 2.f * acc[mt][nt][2], 1e-12f));
                    if (ma1 & mb0) dst[mt][nt][2] += pd;
                    pd = fsqrt_approx(fmaxf(sa1 + sb1 - 2.f * acc[mt][nt][3], 1e-12f));
                    if (ma1 & mb1) dst[mt][nt][3] += pd;
                    acc[mt][nt][0] = 0.f; acc[mt][nt][1] = 0.f;
                    acc[mt][nt][2] = 0.f; acc[mt][nt][3] = 0.f;
                }
            }
        }
        __syncthreads(); // all reads of buf done before it is refilled next iter
    }

    // ---- finalize: dist = sum / popc(maskA & maskB); hardest pos/neg per row & col ----
    const float INFF = __int_as_float(0x7f800000);
    float apc[16], anc[16];
#pragma unroll
    for (int c = 0; c < 16; c++) { apc[c] = 0.f; anc[c] = INFF; }

#pragma unroll
    for (int mt = 0; mt < 2; mt++) {
        int r0 = wm * 32 + mt * 16 + (lane >> 2);
        int r1 = r0 + 8;
        int ta0 = s_tA[r0], ta1 = s_tA[r1];
        int fm0 = s_mA[r0], fm1 = s_mA[r1];
        float ap0 = 0.f, an0 = INFF, ap1 = 0.f, an1 = INFF;
#pragma unroll
        for (int nt = 0; nt < 8; nt++) {
            int c0 = wn * 64 + nt * 8 + (lane & 3) * 2;
            int c1 = c0 + 1;
            int tb0 = s_tB[c0], tb1 = s_tB[c1];
            int gm0 = s_mB[c0], gm1 = s_mB[c1];
            float d00 = __fdividef(dst[mt][nt][0], (float)__popc(fm0 & gm0));
            float d01 = __fdividef(dst[mt][nt][1], (float)__popc(fm0 & gm1));
            float d10 = __fdividef(dst[mt][nt][2], (float)__popc(fm1 & gm0));
            float d11 = __fdividef(dst[mt][nt][3], (float)__popc(fm1 & gm1));
            int ce = nt * 2, co = nt * 2 + 1;
            if (ta0 == tb0) { ap0 = fmaxf(ap0, d00); apc[ce] = fmaxf(apc[ce], d00); }
            else            { an0 = fminf(an0, d00); anc[ce] = fminf(anc[ce], d00); }
            if (ta0 == tb1) { ap0 = fmaxf(ap0, d01); apc[co] = fmaxf(apc[co], d01); }
            else            { an0 = fminf(an0, d01); anc[co] = fminf(anc[co], d01); }
            if (ta1 == tb0) { ap1 = fmaxf(ap1, d10); apc[ce] = fmaxf(apc[ce], d10); }
            else            { an1 = fminf(an1, d10); anc[ce] = fminf(anc[ce], d10); }
            if (ta1 == tb1) { ap1 = fmaxf(ap1, d11); apc[co] = fmaxf(apc[co], d11); }
            else            { an1 = fminf(an1, d11); anc[co] = fminf(anc[co], d11); }
        }
        atomicMax(&s_rAp[r0], __float_as_int(ap0));
        atomicMin(&s_rAn[r0], __float_as_int(an0));
        atomicMax(&s_rAp[r1], __float_as_int(ap1));
        atomicMin(&s_rAn[r1], __float_as_int(an1));
    }
#pragma unroll
    for (int c = 0; c < 16; c++) {
        int cl = wn * 64 + (c >> 1) * 8 + (lane & 3) * 2 + (c & 1);
        atomicMax(&s_cAp[cl], __float_as_int(apc[c]));
        atomicMin(&s_cAn[cl], __float_as_int(anc[c]));
    }
    __syncthreads();
    if (tid < BM) {
        atomicMax(&g_ap[i0 + tid], s_rAp[tid]);
        atomicMin(&g_an[i0 + tid], s_rAn[tid]);
        atomicMax(&g_ap[j0 + tid], s_cAp[tid]); // symmetric side (dupes on diag: harmless)
        atomicMin(&g_an[j0 + tid], s_cAn[tid]);
    }
}

// -------- final scalar reduction --------
__global__ void finish_kernel(float* __restrict__ out) {
    __shared__ float red[8][4];
    int tid = threadIdx.x;
    float ls = 0.f, ps = 0.f, aps = 0.f, ans = 0.f;
    for (int i = tid; i < NN; i += 256) {
        float ap = __int_as_float(g_ap[i]);
        float an = __int_as_float(g_an[i]);
        ls += fmaxf(ap - an + 0.3f, 0.f);
        ps += (an > ap) ? 1.f : 0.f;
        aps += ap; ans += an;
    }
#pragma unroll
    for (int o = 16; o > 0; o >>= 1) {
        ls += __shfl_xor_sync(~0u, ls, o);
        ps += __shfl_xor_sync(~0u, ps, o);
        aps += __shfl_xor_sync(~0u, aps, o);
        ans += __shfl_xor_sync(~0u, ans, o);
    }
    int warp = tid >> 5, lane = tid & 31;
    if (lane == 0) { red[warp][0] = ls; red[warp][1] = ps; red[warp][2] = aps; red[warp][3] = ans; }
    __syncthreads();
    if (tid == 0) {
        float a = 0.f, b = 0.f, c = 0.f, d = 0.f;
#pragma unroll
        for (int w = 0; w < 8; w++) { a += red[w][0]; b += red[w][1]; c += red[w][2]; d += red[w][3]; }
        float inv = 1.0f / (float)NN;
        out[0] = a * inv;  // loss
        out[1] = b * inv;  // prec
        out[2] = c * inv;  // dist_ap mean
        out[3] = d * inv;  // dist_an mean
    }
}

extern "C" void kernel_launch(void* const* d_in, const int* in_sizes, int n_in,
                              void* d_out, int out_size) {
    const float* inputs = (const float*)d_in[0];
    const int* targets = (const int*)d_in[1];
    const int* part_labels = (const int*)d_in[2];
    float* out = (float*)d_out;
    (void)in_sizes; (void)n_in; (void)out_size;

    pack_kernel<<<NN, 256>>>(inputs, part_labels);
    init_kernel<<<(NN + 255) / 256, 256>>>();
    tile_kernel<<<NBLK, 256>>>(targets);
    finish_kernel<<<1, 256>>>(out);
}

// round 6
// speedup vs baseline: 1.0849x; 1.0849x over previous
#include <cuda_runtime.h>
#include <cuda_bf16.h>
#include <stdint.h>

#define NN 2048
#define DD 1024
#define PP 6
#define BM 128
#define BN 128
#define BK 32
#define NT 16                    // NN / BM
#define NBLK (NT * (NT + 1) / 2) // 136 triangular tiles
#define KST (DD / BK)            // 32 k-stages per part
#define STAGES (PP * KST)        // 192 total stages
#define NSTG 4                   // cp.async pipeline depth
#define TILEB (BM * BK * 2)      // 8192 bytes per A or B stage tile
#define DYNB (2 * NSTG * TILEB + 1024)

// -------- scratch (static device globals: allocation-free) --------
__device__ __nv_bfloat16 g_X[(size_t)PP * NN * DD]; // packed [p][n][d] bf16, 25 MB
__device__ float g_sqn[PP * NN];                    // [p][n] squared norms (of bf16 values)
__device__ int g_mask[NN];                          // 6-bit part visibility mask
__device__ int g_ap[NN];                            // float bits, atomicMax (vals >= 0)
__device__ int g_an[NN];                            // float bits, atomicMin

// -------- PTX helpers --------
__device__ __forceinline__ void cp_async16(uint32_t dst, const void* src) {
    asm volatile("cp.async.cg.shared.global [%0], [%1], 16;\n" :: "r"(dst), "l"(src));
}
__device__ __forceinline__ void cp_commit() { asm volatile("cp.async.commit_group;\n"); }
template<int W> __device__ __forceinline__ void cp_wait() {
    asm volatile("cp.async.wait_group %0;\n" :: "n"(W));
}
__device__ __forceinline__ void ldsm_x4(uint32_t r[4], uint32_t addr) {
    asm volatile("ldmatrix.sync.aligned.m8n8.x4.shared.b16 {%0,%1,%2,%3}, [%4];\n"
                 : "=r"(r[0]), "=r"(r[1]), "=r"(r[2]), "=r"(r[3]) : "r"(addr));
}
__device__ __forceinline__ void mma_bf16(float c[4], const uint32_t a[4], uint32_t b0, uint32_t b1) {
    asm volatile("mma.sync.aligned.m16n8k16.row.col.f32.bf16.bf16.f32 "
                 "{%0,%1,%2,%3}, {%4,%5,%6,%7}, {%8,%9}, {%0,%1,%2,%3};\n"
                 : "+f"(c[0]), "+f"(c[1]), "+f"(c[2]), "+f"(c[3])
                 : "r"(a[0]), "r"(a[1]), "r"(a[2]), "r"(a[3]), "r"(b0), "r"(b1));
}
__device__ __forceinline__ float fsqrt_approx(float x) {
    float y; asm("sqrt.approx.f32 %0, %1;" : "=f"(y) : "f"(x)); return y;
}

// Conflict-free swizzled byte offset inside a [128 rows x 32 bf16] stage tile.
// Rows are 64B; 2 rows per 128B line; slot = (kc + 4*(r&1)) ^ ((r>>1)&7).
__device__ __forceinline__ uint32_t tile_off(int r, int kc) {
    return (uint32_t)(((r >> 1) * 128) + ((((kc) + ((r & 1) << 2)) ^ ((r >> 1) & 7)) << 4));
}

// -------- pack: fp32 [n][d][P] -> bf16 [p][n][d]; sqn; masks; init ap/an --------
__global__ void pack_kernel(const float* __restrict__ in, const int* __restrict__ pl) {
    int i = blockIdx.x;
    int tid = threadIdx.x;
    float acc[PP];
#pragma unroll
    for (int p = 0; p < PP; p++) acc[p] = 0.f;
    const float* row = in + (size_t)i * DD * PP;
    for (int dd = tid; dd < DD; dd += 256) {
#pragma unroll
        for (int p = 0; p < PP; p++) {
            float v = row[dd * PP + p];
            __nv_bfloat16 b = __float2bfloat16(v);
            float vb = __bfloat162float(b);
            g_X[((size_t)p * NN + i) * DD + dd] = b;
            acc[p] = fmaf(vb, vb, acc[p]);
        }
    }
    __shared__ float s[8][PP];
    int warp = tid >> 5, lane = tid & 31;
#pragma unroll
    for (int p = 0; p < PP; p++) {
        float v = acc[p];
#pragma unroll
        for (int o = 16; o > 0; o >>= 1) v += __shfl_xor_sync(~0u, v, o);
        if (lane == 0) s[warp][p] = v;
    }
    __syncthreads();
    if (tid < PP) {
        float v = 0.f;
#pragma unroll
        for (int w = 0; w < 8; w++) v += s[w][tid];
        g_sqn[tid * NN + i] = v;
    }
    if (tid == 0) {
        int st = pl[2 * i], en = pl[2 * i + 1];
        g_mask[i] = (int)(((1u << (en + 1)) - 1u) & ~((1u << st) - 1u));
        g_ap[i] = 0;
        g_an[i] = 0x7f800000;
    }
}

// -------- fused tile kernel: 128x128 tile, triangular grid, 4-stage pipeline --------
extern __shared__ __align__(16) char dynsmem[];

__global__ void __launch_bounds__(256, 1)
tile_kernel(const int* __restrict__ targets) {
    __shared__ float s_sqA[PP * BM], s_sqB[PP * BN];
    __shared__ int s_mA[BM], s_mB[BN], s_tA[BM], s_tB[BN];
    __shared__ int s_rAp[BM], s_rAn[BM], s_cAp[BN], s_cAn[BN];

    // triangular block -> (bi, bj), bi <= bj
    int b = blockIdx.x, bi = 0;
    while (b >= NT - bi) { b -= NT - bi; ++bi; }
    int bj = bi + b;
    int i0 = bi * BM, j0 = bj * BN;

    int tid = threadIdx.x;
    int lane = tid & 31, warp = tid >> 5;
    int wm = warp >> 1, wn = warp & 1; // 4x2 warp grid, warp tile 32x64

    // 1024-aligned dynamic smem: NSTG A tiles then NSTG B tiles
    uint32_t dynbase = (uint32_t)__cvta_generic_to_shared(dynsmem);
    dynbase = (dynbase + 1023u) & ~1023u;
    uint32_t aB = dynbase, bB = dynbase + NSTG * TILEB;

    for (int idx = tid; idx < PP * BM; idx += 256) {
        int p = idx >> 7, r = idx & (BM - 1);
        s_sqA[idx] = g_sqn[p * NN + i0 + r];
        s_sqB[idx] = g_sqn[p * NN + j0 + r];
    }
    for (int idx = tid; idx < BM; idx += 256) {
        s_mA[idx] = g_mask[i0 + idx]; s_mB[idx] = g_mask[j0 + idx];
        s_tA[idx] = targets[i0 + idx]; s_tB[idx] = targets[j0 + idx];
        s_rAp[idx] = 0; s_rAn[idx] = 0x7f800000;
        s_cAp[idx] = 0; s_cAn[idx] = 0x7f800000;
    }

    float acc[2][8][4], dst[2][8][4];
#pragma unroll
    for (int mt = 0; mt < 2; mt++)
#pragma unroll
        for (int nt = 0; nt < 8; nt++)
#pragma unroll
            for (int e = 0; e < 4; e++) { acc[mt][nt][e] = 0.f; dst[mt][nt][e] = 0.f; }

    auto issue_load = [&](int s) {
        int slot = s & (NSTG - 1);
        int p = s >> 5;            // s / KST
        int k0 = (s & 31) << 5;    // (s % KST) * BK
        const __nv_bfloat16* gA = g_X + ((size_t)p * NN + i0) * DD + k0;
        const __nv_bfloat16* gB = g_X + ((size_t)p * NN + j0) * DD + k0;
        uint32_t as = aB + slot * TILEB, bs = bB + slot * TILEB;
#pragma unroll
        for (int q = 0; q < 2; q++) {
            int lin = q * 256 + tid;
            int r = lin >> 2, kc = lin & 3;
            uint32_t off = tile_off(r, kc);
            cp_async16(as + off, gA + (size_t)r * DD + (kc << 3));
            cp_async16(bs + off, gB + (size_t)r * DD + (kc << 3));
        }
    };

    int rrow = ((lane >> 3) & 1) * 8 + (lane & 7); // ldmatrix row within 16-row tile
    int chalf = lane >> 4;                         // ldmatrix k-chunk half

    auto compute_stage = [&](int slot) {
        uint32_t as = aB + slot * TILEB, bs = bB + slot * TILEB;
#pragma unroll
        for (int ks = 0; ks < 2; ks++) {
            int kc = ks * 2 + chalf;
            uint32_t a[2][4];
#pragma unroll
            for (int mt = 0; mt < 2; mt++)
                ldsm_x4(a[mt], as + tile_off(wm * 32 + mt * 16 + rrow, kc));
            uint32_t bfr[4][4];
#pragma unroll
            for (int pr = 0; pr < 4; pr++)
                ldsm_x4(bfr[pr], bs + tile_off(wn * 64 + pr * 16 + rrow, kc));
#pragma unroll
            for (int mt = 0; mt < 2; mt++)
#pragma unroll
                for (int nt = 0; nt < 8; nt++)
                    mma_bf16(acc[mt][nt], a[mt], bfr[nt >> 1][nt & 1], bfr[nt >> 1][(nt & 1) + 2]);
        }
    };

    // prologue: 3 stages in flight
#pragma unroll
    for (int c = 0; c < NSTG - 1; c++) { issue_load(c); cp_commit(); }

    for (int s = 0; s < STAGES; s++) {
        if (s + NSTG - 1 < STAGES) issue_load(s + NSTG - 1);
        cp_commit();                    // one group per iter (maybe empty) keeps counts aligned
        cp_wait<NSTG - 1>();            // stage s resident
        __syncthreads();
        compute_stage(s & (NSTG - 1));
        if ((s & 31) == 31) {
            // end of part p: fold gram -> partial distance, reset acc
            int p = s >> 5;
#pragma unroll
            for (int mt = 0; mt < 2; mt++) {
                int r0 = wm * 32 + mt * 16 + (lane >> 2);
                float sa0 = s_sqA[p * BM + r0];
                float sa1 = s_sqA[p * BM + r0 + 8];
                int ma0 = (s_mA[r0] >> p) & 1;
                int ma1 = (s_mA[r0 + 8] >> p) & 1;
#pragma unroll
                for (int nt = 0; nt < 8; nt++) {
                    int c0 = wn * 64 + nt * 8 + (lane & 3) * 2;
                    float sb0 = s_sqB[p * BN + c0], sb1 = s_sqB[p * BN + c0 + 1];
                    int mb0 = (s_mB[c0] >> p) & 1, mb1 = (s_mB[c0 + 1] >> p) & 1;
                    float pd;
                    pd = fsqrt_approx(fmaxf(sa0 + sb0 - 2.f * acc[mt][nt][0], 1e-12f));
                    if (ma0 & mb0) dst[mt][nt][0] += pd;
                    pd = fsqrt_approx(fmaxf(sa0 + sb1 - 2.f * acc[mt][nt][1], 1e-12f));
                    if (ma0 & mb1) dst[mt][nt][1] += pd;
                    pd = fsqrt_approx(fmaxf(sa1 + sb0 - 2.f * acc[mt][nt][2], 1e-12f));
                    if (ma1 & mb0) dst[mt][nt][2] += pd;
                    pd = fsqrt_approx(fmaxf(sa1 + sb1 - 2.f * acc[mt][nt][3], 1e-12f));
                    if (ma1 & mb1) dst[mt][nt][3] += pd;
                    acc[mt][nt][0] = 0.f; acc[mt][nt][1] = 0.f;
                    acc[mt][nt][2] = 0.f; acc[mt][nt][3] = 0.f;
                }
            }
        }
        __syncthreads(); // all reads of slot done before its refill next iters
    }

    // ---- finalize: dist = sum / popc(maskA & maskB); hardest pos/neg per row & col ----
    const float INFF = __int_as_float(0x7f800000);
    float apc[16], anc[16];
#pragma unroll
    for (int c = 0; c < 16; c++) { apc[c] = 0.f; anc[c] = INFF; }

#pragma unroll
    for (int mt = 0; mt < 2; mt++) {
        int r0 = wm * 32 + mt * 16 + (lane >> 2);
        int r1 = r0 + 8;
        int ta0 = s_tA[r0], ta1 = s_tA[r1];
        int fm0 = s_mA[r0], fm1 = s_mA[r1];
        float ap0 = 0.f, an0 = INFF, ap1 = 0.f, an1 = INFF;
#pragma unroll
        for (int nt = 0; nt < 8; nt++) {
            int c0 = wn * 64 + nt * 8 + (lane & 3) * 2;
            int c1 = c0 + 1;
            int tb0 = s_tB[c0], tb1 = s_tB[c1];
            int gm0 = s_mB[c0], gm1 = s_mB[c1];
            float d00 = __fdividef(dst[mt][nt][0], (float)__popc(fm0 & gm0));
            float d01 = __fdividef(dst[mt][nt][1], (float)__popc(fm0 & gm1));
            float d10 = __fdividef(dst[mt][nt][2], (float)__popc(fm1 & gm0));
            float d11 = __fdividef(dst[mt][nt][3], (float)__popc(fm1 & gm1));
            int ce = nt * 2, co = nt * 2 + 1;
            if (ta0 == tb0) { ap0 = fmaxf(ap0, d00); apc[ce] = fmaxf(apc[ce], d00); }
            else            { an0 = fminf(an0, d00); anc[ce] = fminf(anc[ce], d00); }
            if (ta0 == tb1) { ap0 = fmaxf(ap0, d01); apc[co] = fmaxf(apc[co], d01); }
            else            { an0 = fminf(an0, d01); anc[co] = fminf(anc[co], d01); }
            if (ta1 == tb0) { ap1 = fmaxf(ap1, d10); apc[ce] = fmaxf(apc[ce], d10); }
            else            { an1 = fminf(an1, d10); anc[ce] = fminf(anc[ce], d10); }
            if (ta1 == tb1) { ap1 = fmaxf(ap1, d11); apc[co] = fmaxf(apc[co], d11); }
            else            { an1 = fminf(an1, d11); anc[co] = fminf(anc[co], d11); }
        }
        atomicMax(&s_rAp[r0], __float_as_int(ap0));
        atomicMin(&s_rAn[r0], __float_as_int(an0));
        atomicMax(&s_rAp[r1], __float_as_int(ap1));
        atomicMin(&s_rAn[r1], __float_as_int(an1));
    }
#pragma unroll
    for (int c = 0; c < 16; c++) {
        int cl = wn * 64 + (c >> 1) * 8 + (lane & 3) * 2 + (c & 1);
        atomicMax(&s_cAp[cl], __float_as_int(apc[c]));
        atomicMin(&s_cAn[cl], __float_as_int(anc[c]));
    }
    __syncthreads();
    if (tid < BM) {
        atomicMax(&g_ap[i0 + tid], s_rAp[tid]);
        atomicMin(&g_an[i0 + tid], s_rAn[tid]);
        atomicMax(&g_ap[j0 + tid], s_cAp[tid]); // symmetric side (diag dupes harmless)
        atomicMin(&g_an[j0 + tid], s_cAn[tid]);
    }
}

// -------- final scalar reduction (1024 threads) --------
__global__ void finish_kernel(float* __restrict__ out) {
    __shared__ float red[32][4];
    int tid = threadIdx.x;
    float ls = 0.f, ps = 0.f, aps = 0.f, ans = 0.f;
    for (int i = tid; i < NN; i += 1024) {
        float ap = __int_as_float(g_ap[i]);
        float an = __int_as_float(g_an[i]);
        ls += fmaxf(ap - an + 0.3f, 0.f);
        ps += (an > ap) ? 1.f : 0.f;
        aps += ap; ans += an;
    }
#pragma unroll
    for (int o = 16; o > 0; o >>= 1) {
        ls += __shfl_xor_sync(~0u, ls, o);
        ps += __shfl_xor_sync(~0u, ps, o);
        aps += __shfl_xor_sync(~0u, aps, o);
        ans += __shfl_xor_sync(~0u, ans, o);
    }
    int warp = tid >> 5, lane = tid & 31;
    if (lane == 0) { red[warp][0] = ls; red[warp][1] = ps; red[warp][2] = aps; red[warp][3] = ans; }
    __syncthreads();
    if (tid == 0) {
        float a = 0.f, bb = 0.f, cc = 0.f, dd = 0.f;
#pragma unroll
        for (int w = 0; w < 32; w++) { a += red[w][0]; bb += red[w][1]; cc += red[w][2]; dd += red[w][3]; }
        float inv = 1.0f / (float)NN;
        out[0] = a * inv;  // loss
        out[1] = bb * inv; // prec
        out[2] = cc * inv; // dist_ap mean
        out[3] = dd * inv; // dist_an mean
    }
}

extern "C" void kernel_launch(void* const* d_in, const int* in_sizes, int n_in,
                              void* d_out, int out_size) {
    const float* inputs = (const float*)d_in[0];
    const int* targets = (const int*)d_in[1];
    const int* part_labels = (const int*)d_in[2];
    float* out = (float*)d_out;
    (void)in_sizes; (void)n_in; (void)out_size;

    cudaFuncSetAttribute(tile_kernel, cudaFuncAttributeMaxDynamicSharedMemorySize, DYNB);

    pack_kernel<<<NN, 256>>>(inputs, part_labels);
    tile_kernel<<<NBLK, 256, DYNB>>>(targets);
    finish_kernel<<<1, 1024>>>(out);
}